// round 2
// baseline (speedup 1.0000x reference)
#include <cuda_runtime.h>
#include <math.h>

// Problem shape (fixed)
constexpr int Bb  = 4;
constexpr int Ss  = 2048;
constexpr int Dd  = 1024;
constexpr int Hh  = 16;
constexpr int DHh = 64;
constexpr int Mrows = Bb * Ss;          // 8192
constexpr int QKV_N = 3 * Hh * DHh;     // 3072

// Scratch (device globals: allocation-free, allowed)
__device__ float g_qkv[(size_t)Mrows * QKV_N];   // [b,s,3,h,e]
__device__ float g_ans[(size_t)Mrows * Hh * DHh];// [b,s,h,e]

// ---------------------------------------------------------------------------
// SGEMM with bias: C[M,N] = A[M,K] @ B[K,N] + bias[N]
// 128x128x16 tiles, 8x8 per thread, 256 threads.
// Software-pipelined: next tile's global loads issued before current compute.
// ---------------------------------------------------------------------------
template <int BM, int BN, int BK, int TM, int TN>
__global__ __launch_bounds__(256, 2)
void sgemm_bias(const float* __restrict__ A, const float* __restrict__ Bm,
                const float* __restrict__ bias, float* __restrict__ C,
                int M, int N, int K) {
    constexpr int NA = (BM * BK) / (4 * 256);   // float4 A-loads per thread (2)
    constexpr int NB = (BK * BN) / (4 * 256);   // float4 B-loads per thread (2)

    __shared__ float As[BK][BM];
    __shared__ float Bs[BK][BN];

    const int tid = threadIdx.x;
    const int bx = blockIdx.x, by = blockIdx.y;
    const int tx = tid % (BN / TN);     // 0..15
    const int ty = tid / (BN / TN);     // 0..15

    float acc[TM][TN] = {};

    const float* Ag = A + (size_t)by * BM * K;
    const float* Bg = Bm + (size_t)bx * BN;

    // Per-thread fixed load coordinates
    int arow[NA], acol4[NA];
    int brow[NB], bcol4[NB];
    #pragma unroll
    for (int it = 0; it < NA; ++it) {
        int f4 = tid + it * 256;
        arow[it]  = f4 / (BK / 4);
        acol4[it] = f4 % (BK / 4);
    }
    #pragma unroll
    for (int it = 0; it < NB; ++it) {
        int f4 = tid + it * 256;
        brow[it]  = f4 / (BN / 4);
        bcol4[it] = f4 % (BN / 4);
    }

    float4 ra[NA], rb[NB];

    // Prologue: fetch tile 0
    #pragma unroll
    for (int it = 0; it < NA; ++it)
        ra[it] = *(const float4*)(Ag + (size_t)arow[it] * K + acol4[it] * 4);
    #pragma unroll
    for (int it = 0; it < NB; ++it)
        rb[it] = *(const float4*)(Bg + (size_t)brow[it] * N + bcol4[it] * 4);

    for (int k0 = 0; k0 < K; k0 += BK) {
        // Commit prefetched tile to smem
        #pragma unroll
        for (int it = 0; it < NA; ++it) {
            As[acol4[it] * 4 + 0][arow[it]] = ra[it].x;
            As[acol4[it] * 4 + 1][arow[it]] = ra[it].y;
            As[acol4[it] * 4 + 2][arow[it]] = ra[it].z;
            As[acol4[it] * 4 + 3][arow[it]] = ra[it].w;
        }
        #pragma unroll
        for (int it = 0; it < NB; ++it)
            *(float4*)(&Bs[brow[it]][bcol4[it] * 4]) = rb[it];
        __syncthreads();

        // Issue next tile's global loads (overlap with compute below)
        const int kn = k0 + BK;
        if (kn < K) {
            #pragma unroll
            for (int it = 0; it < NA; ++it)
                ra[it] = *(const float4*)(Ag + (size_t)arow[it] * K + kn + acol4[it] * 4);
            #pragma unroll
            for (int it = 0; it < NB; ++it)
                rb[it] = *(const float4*)(Bg + (size_t)(kn + brow[it]) * N + bcol4[it] * 4);
        }

        // Compute on current tile
        #pragma unroll
        for (int kk = 0; kk < BK; ++kk) {
            float a[TM], b[TN];
            #pragma unroll
            for (int i = 0; i < TM; ++i) a[i] = As[kk][ty * TM + i];
            #pragma unroll
            for (int j = 0; j < TN; ++j) b[j] = Bs[kk][tx * TN + j];
            #pragma unroll
            for (int i = 0; i < TM; ++i)
                #pragma unroll
                for (int j = 0; j < TN; ++j)
                    acc[i][j] += a[i] * b[j];
        }
        __syncthreads();
    }

    // Epilogue with bias, vectorized stores
    #pragma unroll
    for (int i = 0; i < TM; ++i) {
        int row = by * BM + ty * TM + i;
        #pragma unroll
        for (int j = 0; j < TN; j += 4) {
            int col = bx * BN + tx * TN + j;
            float4 v;
            v.x = acc[i][j + 0] + bias[col + 0];
            v.y = acc[i][j + 1] + bias[col + 1];
            v.z = acc[i][j + 2] + bias[col + 2];
            v.w = acc[i][j + 3] + bias[col + 3];
            *(float4*)(C + (size_t)row * N + col) = v;
        }
    }
}

// ---------------------------------------------------------------------------
// Causal flash attention, fp32. One block per (qtile, h, b).
// BR=BC=64, 256 threads (16x16), 4x4 per thread.
// ---------------------------------------------------------------------------
constexpr int BR = 64;
constexpr int BC = 64;
constexpr int SPAD = DHh + 4;   // 68 floats/row, float4-aligned

__global__ __launch_bounds__(256, 2)
void flash_attn(const float* __restrict__ qkv, float* __restrict__ ans) {
    __shared__ float Qs[BR][SPAD];
    __shared__ float Ks[BC][SPAD];   // reused as P after scores computed
    __shared__ float Vs[BC][SPAD];

    const int qt = blockIdx.x;
    const int h  = blockIdx.y;
    const int b  = blockIdx.z;
    const int q0 = qt * BR;

    const int tid = threadIdx.x;
    const int tx = tid % 16;    // col group
    const int ty = tid / 16;    // row group

    // Load Q tile (t=0)
    for (int f4 = tid; f4 < BR * (DHh / 4); f4 += 256) {
        int r  = f4 / (DHh / 4);
        int e4 = f4 % (DHh / 4);
        *(float4*)(&Qs[r][e4 * 4]) = *(const float4*)(
            qkv + (size_t)(b * Ss + q0 + r) * QKV_N + 0 * Hh * DHh + h * DHh + e4 * 4);
    }

    float4 o[4];
    float m_i[4], l_i[4];
    #pragma unroll
    for (int i = 0; i < 4; ++i) {
        o[i] = make_float4(0.f, 0.f, 0.f, 0.f);
        m_i[i] = -INFINITY;
        l_i[i] = 0.f;
    }

    for (int kt = 0; kt <= qt; ++kt) {
        const int k0 = kt * BC;
        __syncthreads();   // protect Ks(P)/Vs from previous iteration's reads
        // Load K (t=1) and V (t=2)
        for (int f4 = tid; f4 < BC * (DHh / 4); f4 += 256) {
            int r  = f4 / (DHh / 4);
            int e4 = f4 % (DHh / 4);
            size_t base = (size_t)(b * Ss + k0 + r) * QKV_N + h * DHh + e4 * 4;
            *(float4*)(&Ks[r][e4 * 4]) = *(const float4*)(qkv + base + 1 * Hh * DHh);
            *(float4*)(&Vs[r][e4 * 4]) = *(const float4*)(qkv + base + 2 * Hh * DHh);
        }
        __syncthreads();

        // S = Q @ K^T
        float s[4][4] = {};
        #pragma unroll
        for (int e4 = 0; e4 < DHh / 4; ++e4) {
            float4 q4[4], k4[4];
            #pragma unroll
            for (int i = 0; i < 4; ++i) q4[i] = *(float4*)(&Qs[ty * 4 + i][e4 * 4]);
            #pragma unroll
            for (int j = 0; j < 4; ++j) k4[j] = *(float4*)(&Ks[tx * 4 + j][e4 * 4]);
            #pragma unroll
            for (int i = 0; i < 4; ++i)
                #pragma unroll
                for (int j = 0; j < 4; ++j)
                    s[i][j] += q4[i].x * k4[j].x + q4[i].y * k4[j].y
                             + q4[i].z * k4[j].z + q4[i].w * k4[j].w;
        }

        const bool diag = (kt == qt);
        #pragma unroll
        for (int i = 0; i < 4; ++i)
            #pragma unroll
            for (int j = 0; j < 4; ++j) {
                s[i][j] *= 0.125f;  // 1/sqrt(64)
                if (diag && (k0 + tx * 4 + j > q0 + ty * 4 + i)) s[i][j] = -1e30f;
            }

        // Online softmax (row reduction across the 16 tx lanes)
        float p[4][4];
        #pragma unroll
        for (int i = 0; i < 4; ++i) {
            float mx = fmaxf(fmaxf(s[i][0], s[i][1]), fmaxf(s[i][2], s[i][3]));
            #pragma unroll
            for (int off = 8; off >= 1; off >>= 1)
                mx = fmaxf(mx, __shfl_xor_sync(0xffffffffu, mx, off));
            float mnew = fmaxf(m_i[i], mx);
            float rs = 0.f;
            #pragma unroll
            for (int j = 0; j < 4; ++j) {
                p[i][j] = __expf(s[i][j] - mnew);
                rs += p[i][j];
            }
            #pragma unroll
            for (int off = 8; off >= 1; off >>= 1)
                rs += __shfl_xor_sync(0xffffffffu, rs, off);
            float alpha = __expf(m_i[i] - mnew);
            l_i[i] = l_i[i] * alpha + rs;
            m_i[i] = mnew;
            o[i].x *= alpha; o[i].y *= alpha; o[i].z *= alpha; o[i].w *= alpha;
        }

        __syncthreads();  // done reading Ks as K
        // Write P into Ks buffer
        #pragma unroll
        for (int i = 0; i < 4; ++i)
            #pragma unroll
            for (int j = 0; j < 4; ++j)
                Ks[ty * 4 + i][tx * 4 + j] = p[i][j];
        __syncthreads();

        // O += P @ V
        #pragma unroll
        for (int k = 0; k < BC; ++k) {
            float4 v4 = *(float4*)(&Vs[k][tx * 4]);
            #pragma unroll
            for (int i = 0; i < 4; ++i) {
                float pv = Ks[ty * 4 + i][k];
                o[i].x += pv * v4.x;
                o[i].y += pv * v4.y;
                o[i].z += pv * v4.z;
                o[i].w += pv * v4.w;
            }
        }
    }

    // Normalize and write answers [b, s, h, e]
    #pragma unroll
    for (int i = 0; i < 4; ++i) {
        float inv = 1.f / l_i[i];
        int row = q0 + ty * 4 + i;
        float4 v = make_float4(o[i].x * inv, o[i].y * inv, o[i].z * inv, o[i].w * inv);
        *(float4*)(ans + ((size_t)(b * Ss + row) * Hh + h) * DHh + tx * 4) = v;
    }
}

// ---------------------------------------------------------------------------
// Launch
// ---------------------------------------------------------------------------
extern "C" void kernel_launch(void* const* d_in, const int* in_sizes, int n_in,
                              void* d_out, int out_size) {
    const float* x     = (const float*)d_in[0];   // (B,S,D)
    const float* w_qkv = (const float*)d_in[1];   // (D,3,H,DH) == (1024,3072)
    const float* b_qkv = (const float*)d_in[2];   // (3,H,DH)   == (3072)
    const float* w_out = (const float*)d_in[3];   // (H,DH,D)   == (1024,1024)
    const float* b_out = (const float*)d_in[4];   // (D)
    float* out = (float*)d_out;                   // (B,S,D)

    void* qkv_ptr = nullptr;
    void* ans_ptr = nullptr;
    cudaGetSymbolAddress(&qkv_ptr, g_qkv);
    cudaGetSymbolAddress(&ans_ptr, g_ans);
    float* qkv = (float*)qkv_ptr;
    float* ans = (float*)ans_ptr;

    // 1) QKV projection: [8192,1024] @ [1024,3072] + bias
    {
        dim3 grid(QKV_N / 128, Mrows / 128);
        sgemm_bias<128, 128, 16, 8, 8><<<grid, 256>>>(
            x, w_qkv, b_qkv, qkv, Mrows, QKV_N, Dd);
    }

    // 2) Causal flash attention
    {
        dim3 grid(Ss / BR, Hh, Bb);
        flash_attn<<<grid, 256>>>(qkv, ans);
    }

    // 3) Output projection: [8192,1024] @ [1024,1024] + bias
    {
        dim3 grid(Dd / 128, Mrows / 128);
        sgemm_bias<128, 128, 16, 8, 8><<<grid, 256>>>(
            ans, w_out, b_out, out, Mrows, Dd, Dd);
    }
}

// round 10
// speedup vs baseline: 1.4173x; 1.4173x over previous
#include <cuda_runtime.h>
#include <math.h>

// Problem shape (fixed)
constexpr int Bb  = 4;
constexpr int Ss  = 2048;
constexpr int Dd  = 1024;
constexpr int Hh  = 16;
constexpr int DHh = 64;
constexpr int Mrows = Bb * Ss;          // 8192
constexpr int QKV_N = 3 * Hh * DHh;     // 3072

// Scratch (device globals: allocation-free, allowed)
__device__ float g_qkv[(size_t)Mrows * QKV_N];   // [b,s,3,h,e]
__device__ float g_ans[(size_t)Mrows * Hh * DHh];// [b,s,h,e]

// ===========================================================================
// Portable tensor-core helpers (compute_103 family target — NO tcgen05/TMA)
// ===========================================================================
__device__ __forceinline__ unsigned f2tf32(float x) {
    unsigned u;
    asm("cvt.rna.tf32.f32 %0, %1;" : "=r"(u) : "f"(x));
    return u;
}
// m16n8k8 tf32 MMA: D = A@B + D (A row-major 16x8, B col-major 8x8, fp32 accum)
__device__ __forceinline__ void mma_tf32(float* c, const unsigned* a, const unsigned* b) {
    asm volatile(
        "mma.sync.aligned.m16n8k8.row.col.f32.tf32.tf32.f32 "
        "{%0,%1,%2,%3}, {%4,%5,%6,%7}, {%8,%9}, {%0,%1,%2,%3};\n"
        : "+f"(c[0]), "+f"(c[1]), "+f"(c[2]), "+f"(c[3])
        : "r"(a[0]), "r"(a[1]), "r"(a[2]), "r"(a[3]), "r"(b[0]), "r"(b[1]));
}

// ===========================================================================
// tf32 mma.sync GEMM with bias: C[M,N] = A[M,K] @ B[K,N] + bias[N]
// CTA 128x128x32, 8 warps (2x4), warp tile 64x32, double-buffered smem.
// grid = (N/128, M/128), 256 threads.
// ===========================================================================
constexpr int BM = 128, BN = 128, BK = 32;
constexpr int ASTR = BK + 4;                 // 36 floats: stride%32banks==4 -> A frags conflict-free
constexpr int BSTR = BN + 8;                 // 136 floats: stride%32banks==8 -> B frags conflict-free
constexpr int ABUF = BM * ASTR;              // 4608 words
constexpr int BBUF = BK * BSTR;              // 4352 words
constexpr unsigned SMEM_TOTAL_G = 2u * (ABUF + BBUF) * 4u;   // 71680 bytes

__global__ __launch_bounds__(256)
void tf32_mma_gemm_bias(const float* __restrict__ A, const float* __restrict__ Bm,
                        const float* __restrict__ bias, float* __restrict__ C,
                        int M, int N, int K) {
    extern __shared__ unsigned smemu[];

    const int tid  = threadIdx.x;
    const int warp = tid >> 5;
    const int lane = tid & 31;
    const int wm   = warp >> 2;      // 0..1 (64-row half)
    const int wn   = warp & 3;       // 0..3 (32-col quarter)
    const int g    = lane >> 2;      // 0..7
    const int t    = lane & 3;       // 0..3

    const float* Ag = A  + (size_t)blockIdx.y * BM * K;
    const float* Bg = Bm + (size_t)blockIdx.x * BN;

    // Per-thread load coords (fixed)
    //  A tile: 128 rows x 8 float4
    //  B tile: 32 rows x 32 float4
    int arow[4], ac4[4], brow[4], bc4[4];
    #pragma unroll
    for (int i = 0; i < 4; ++i) {
        int f4 = tid + i * 256;
        arow[i] = f4 >> 3;  ac4[i] = f4 & 7;
        brow[i] = f4 >> 5;  bc4[i] = f4 & 31;
    }

    float acc[4][4][4];
    #pragma unroll
    for (int mt = 0; mt < 4; ++mt)
        #pragma unroll
        for (int nt = 0; nt < 4; ++nt)
            #pragma unroll
            for (int j = 0; j < 4; ++j) acc[mt][nt][j] = 0.f;

    const int nchunks = K / BK;    // 32
    float4 ra[4], rb[4];

    // Prologue: LDG chunk 0
    #pragma unroll
    for (int i = 0; i < 4; ++i)
        ra[i] = *(const float4*)(Ag + (size_t)arow[i] * K + ac4[i] * 4);
    #pragma unroll
    for (int i = 0; i < 4; ++i)
        rb[i] = *(const float4*)(Bg + (size_t)brow[i] * N + bc4[i] * 4);

    // Commit chunk 0 into buffer 0 (tf32-rounded once, at STS)
    {
        unsigned* sA = smemu;
        unsigned* sB = smemu + ABUF;
        #pragma unroll
        for (int i = 0; i < 4; ++i) {
            unsigned* d = sA + arow[i] * ASTR + ac4[i] * 4;
            d[0] = f2tf32(ra[i].x); d[1] = f2tf32(ra[i].y);
            d[2] = f2tf32(ra[i].z); d[3] = f2tf32(ra[i].w);
        }
        #pragma unroll
        for (int i = 0; i < 4; ++i) {
            unsigned* d = sB + brow[i] * BSTR + bc4[i] * 4;
            d[0] = f2tf32(rb[i].x); d[1] = f2tf32(rb[i].y);
            d[2] = f2tf32(rb[i].z); d[3] = f2tf32(rb[i].w);
        }
    }
    __syncthreads();

    for (int c = 0; c < nchunks; ++c) {
        // Prefetch next chunk's global data (overlaps with compute)
        if (c + 1 < nchunks) {
            const int kn = (c + 1) * BK;
            #pragma unroll
            for (int i = 0; i < 4; ++i)
                ra[i] = *(const float4*)(Ag + (size_t)arow[i] * K + kn + ac4[i] * 4);
            #pragma unroll
            for (int i = 0; i < 4; ++i)
                rb[i] = *(const float4*)(Bg + (size_t)(kn + brow[i]) * N + bc4[i] * 4);
        }

        // Compute on buffer c&1
        {
            const unsigned* sA = smemu + (c & 1) * (ABUF + BBUF);
            const unsigned* sB = sA + ABUF;
            #pragma unroll
            for (int ks = 0; ks < 4; ++ks) {
                unsigned af[4][4], bf[4][2];
                #pragma unroll
                for (int mt = 0; mt < 4; ++mt) {
                    const int base = (wm * 64 + mt * 16 + g) * ASTR + ks * 8 + t;
                    af[mt][0] = sA[base];
                    af[mt][1] = sA[base + 8 * ASTR];
                    af[mt][2] = sA[base + 4];
                    af[mt][3] = sA[base + 8 * ASTR + 4];
                }
                #pragma unroll
                for (int nt = 0; nt < 4; ++nt) {
                    const int bbase = (ks * 8 + t) * BSTR + wn * 32 + nt * 8 + g;
                    bf[nt][0] = sB[bbase];
                    bf[nt][1] = sB[bbase + 4 * BSTR];
                }
                #pragma unroll
                for (int mt = 0; mt < 4; ++mt)
                    #pragma unroll
                    for (int nt = 0; nt < 4; ++nt)
                        mma_tf32(acc[mt][nt], af[mt], bf[nt]);
            }
        }

        // Commit prefetched chunk into the other buffer
        if (c + 1 < nchunks) {
            unsigned* sA = smemu + ((c + 1) & 1) * (ABUF + BBUF);
            unsigned* sB = sA + ABUF;
            #pragma unroll
            for (int i = 0; i < 4; ++i) {
                unsigned* d = sA + arow[i] * ASTR + ac4[i] * 4;
                d[0] = f2tf32(ra[i].x); d[1] = f2tf32(ra[i].y);
                d[2] = f2tf32(ra[i].z); d[3] = f2tf32(ra[i].w);
            }
            #pragma unroll
            for (int i = 0; i < 4; ++i) {
                unsigned* d = sB + brow[i] * BSTR + bc4[i] * 4;
                d[0] = f2tf32(rb[i].x); d[1] = f2tf32(rb[i].y);
                d[2] = f2tf32(rb[i].z); d[3] = f2tf32(rb[i].w);
            }
            __syncthreads();
        }
    }

    // Epilogue: bias + float2 stores
    const int rowb = blockIdx.y * BM;
    const int colb = blockIdx.x * BN;
    #pragma unroll
    for (int mt = 0; mt < 4; ++mt) {
        const int row0 = rowb + wm * 64 + mt * 16 + g;
        #pragma unroll
        for (int nt = 0; nt < 4; ++nt) {
            const int col = colb + wn * 32 + nt * 8 + 2 * t;
            float2 bb = *(const float2*)(bias + col);
            float2 v0, v1;
            v0.x = acc[mt][nt][0] + bb.x;  v0.y = acc[mt][nt][1] + bb.y;
            v1.x = acc[mt][nt][2] + bb.x;  v1.y = acc[mt][nt][3] + bb.y;
            *(float2*)(C + (size_t)row0 * N + col)       = v0;
            *(float2*)(C + (size_t)(row0 + 8) * N + col) = v1;
        }
    }
}

// ---------------------------------------------------------------------------
// Causal flash attention, fp32 (unchanged — passing at rel_err 9.2e-7).
// ---------------------------------------------------------------------------
constexpr int BR = 64;
constexpr int BC = 64;
constexpr int SPAD = DHh + 4;

__global__ __launch_bounds__(256, 2)
void flash_attn(const float* __restrict__ qkv, float* __restrict__ ans) {
    __shared__ float Qs[BR][SPAD];
    __shared__ float Ks[BC][SPAD];
    __shared__ float Vs[BC][SPAD];

    const int qt = blockIdx.x;
    const int h  = blockIdx.y;
    const int b  = blockIdx.z;
    const int q0 = qt * BR;

    const int tid = threadIdx.x;
    const int tx = tid % 16;
    const int ty = tid / 16;

    for (int f4 = tid; f4 < BR * (DHh / 4); f4 += 256) {
        int r  = f4 / (DHh / 4);
        int e4 = f4 % (DHh / 4);
        *(float4*)(&Qs[r][e4 * 4]) = *(const float4*)(
            qkv + (size_t)(b * Ss + q0 + r) * QKV_N + h * DHh + e4 * 4);
    }

    float4 o[4];
    float m_i[4], l_i[4];
    #pragma unroll
    for (int i = 0; i < 4; ++i) {
        o[i] = make_float4(0.f, 0.f, 0.f, 0.f);
        m_i[i] = -INFINITY;
        l_i[i] = 0.f;
    }

    for (int kt = 0; kt <= qt; ++kt) {
        const int k0 = kt * BC;
        __syncthreads();
        for (int f4 = tid; f4 < BC * (DHh / 4); f4 += 256) {
            int r  = f4 / (DHh / 4);
            int e4 = f4 % (DHh / 4);
            size_t base = (size_t)(b * Ss + k0 + r) * QKV_N + h * DHh + e4 * 4;
            *(float4*)(&Ks[r][e4 * 4]) = *(const float4*)(qkv + base + 1 * Hh * DHh);
            *(float4*)(&Vs[r][e4 * 4]) = *(const float4*)(qkv + base + 2 * Hh * DHh);
        }
        __syncthreads();

        float s[4][4] = {};
        #pragma unroll
        for (int e4 = 0; e4 < DHh / 4; ++e4) {
            float4 q4[4], k4[4];
            #pragma unroll
            for (int i = 0; i < 4; ++i) q4[i] = *(float4*)(&Qs[ty * 4 + i][e4 * 4]);
            #pragma unroll
            for (int j = 0; j < 4; ++j) k4[j] = *(float4*)(&Ks[tx * 4 + j][e4 * 4]);
            #pragma unroll
            for (int i = 0; i < 4; ++i)
                #pragma unroll
                for (int j = 0; j < 4; ++j)
                    s[i][j] += q4[i].x * k4[j].x + q4[i].y * k4[j].y
                             + q4[i].z * k4[j].z + q4[i].w * k4[j].w;
        }

        const bool diag = (kt == qt);
        #pragma unroll
        for (int i = 0; i < 4; ++i)
            #pragma unroll
            for (int j = 0; j < 4; ++j) {
                s[i][j] *= 0.125f;
                if (diag && (k0 + tx * 4 + j > q0 + ty * 4 + i)) s[i][j] = -1e30f;
            }

        float p[4][4];
        #pragma unroll
        for (int i = 0; i < 4; ++i) {
            float mx = fmaxf(fmaxf(s[i][0], s[i][1]), fmaxf(s[i][2], s[i][3]));
            #pragma unroll
            for (int off = 8; off >= 1; off >>= 1)
                mx = fmaxf(mx, __shfl_xor_sync(0xffffffffu, mx, off));
            float mnew = fmaxf(m_i[i], mx);
            float rs = 0.f;
            #pragma unroll
            for (int j = 0; j < 4; ++j) {
                p[i][j] = __expf(s[i][j] - mnew);
                rs += p[i][j];
            }
            #pragma unroll
            for (int off = 8; off >= 1; off >>= 1)
                rs += __shfl_xor_sync(0xffffffffu, rs, off);
            float alpha = __expf(m_i[i] - mnew);
            l_i[i] = l_i[i] * alpha + rs;
            m_i[i] = mnew;
            o[i].x *= alpha; o[i].y *= alpha; o[i].z *= alpha; o[i].w *= alpha;
        }

        __syncthreads();
        #pragma unroll
        for (int i = 0; i < 4; ++i)
            #pragma unroll
            for (int j = 0; j < 4; ++j)
                Ks[ty * 4 + i][tx * 4 + j] = p[i][j];
        __syncthreads();

        #pragma unroll
        for (int k = 0; k < BC; ++k) {
            float4 v4 = *(float4*)(&Vs[k][tx * 4]);
            #pragma unroll
            for (int i = 0; i < 4; ++i) {
                float pv = Ks[ty * 4 + i][k];
                o[i].x += pv * v4.x;
                o[i].y += pv * v4.y;
                o[i].z += pv * v4.z;
                o[i].w += pv * v4.w;
            }
        }
    }

    #pragma unroll
    for (int i = 0; i < 4; ++i) {
        float inv = 1.f / l_i[i];
        int row = q0 + ty * 4 + i;
        float4 v = make_float4(o[i].x * inv, o[i].y * inv, o[i].z * inv, o[i].w * inv);
        *(float4*)(ans + ((size_t)(b * Ss + row) * Hh + h) * DHh + tx * 4) = v;
    }
}

// ---------------------------------------------------------------------------
// Launch
// ---------------------------------------------------------------------------
extern "C" void kernel_launch(void* const* d_in, const int* in_sizes, int n_in,
                              void* d_out, int out_size) {
    const float* x     = (const float*)d_in[0];
    const float* w_qkv = (const float*)d_in[1];
    const float* b_qkv = (const float*)d_in[2];
    const float* w_out = (const float*)d_in[3];
    const float* b_out = (const float*)d_in[4];
    float* out = (float*)d_out;

    void* qkv_ptr = nullptr;
    void* ans_ptr = nullptr;
    cudaGetSymbolAddress(&qkv_ptr, g_qkv);
    cudaGetSymbolAddress(&ans_ptr, g_ans);
    float* qkv = (float*)qkv_ptr;
    float* ans = (float*)ans_ptr;

    cudaFuncSetAttribute(tf32_mma_gemm_bias,
                         cudaFuncAttributeMaxDynamicSharedMemorySize,
                         (int)SMEM_TOTAL_G);

    // 1) QKV projection: [8192,1024] @ [1024,3072] + bias  (tf32 mma.sync)
    {
        dim3 grid(QKV_N / 128, Mrows / 128);
        tf32_mma_gemm_bias<<<grid, 256, SMEM_TOTAL_G>>>(
            x, w_qkv, b_qkv, qkv, Mrows, QKV_N, Dd);
    }

    // 2) Causal flash attention (fp32)
    {
        dim3 grid(Ss / BR, Hh, Bb);
        flash_attn<<<grid, 256>>>(qkv, ans);
    }

    // 3) Output projection: [8192,1024] @ [1024,1024] + bias  (tf32 mma.sync)
    {
        dim3 grid(Dd / 128, Mrows / 128);
        tf32_mma_gemm_bias<<<grid, 256, SMEM_TOTAL_G>>>(
            ans, w_out, b_out, out, Mrows, Dd, Dd);
    }
}

// round 13
// speedup vs baseline: 3.3084x; 2.3343x over previous
#include <cuda_runtime.h>
#include <math.h>

// Problem shape (fixed)
constexpr int Bb  = 4;
constexpr int Ss  = 2048;
constexpr int Dd  = 1024;
constexpr int Hh  = 16;
constexpr int DHh = 64;
constexpr int Mrows = Bb * Ss;          // 8192
constexpr int QKV_N = 3 * Hh * DHh;     // 3072

// Scratch (device globals: allocation-free, allowed)
__device__ float g_qkv[(size_t)Mrows * QKV_N];   // [b,s,3,h,e]
__device__ float g_ans[(size_t)Mrows * Hh * DHh];// [b,s,h,e]

// ===========================================================================
// Portable tensor-core helpers (compute_103 family target — NO tcgen05/TMA)
// ===========================================================================
__device__ __forceinline__ unsigned f2tf32(float x) {
    unsigned u;
    asm("cvt.rna.tf32.f32 %0, %1;" : "=r"(u) : "f"(x));
    return u;
}
// m16n8k8 tf32 MMA: D = A@B + D (A row-major 16x8, B col-major 8x8, fp32 accum)
__device__ __forceinline__ void mma_tf32(float* c, const unsigned* a, const unsigned* b) {
    asm volatile(
        "mma.sync.aligned.m16n8k8.row.col.f32.tf32.tf32.f32 "
        "{%0,%1,%2,%3}, {%4,%5,%6,%7}, {%8,%9}, {%0,%1,%2,%3};\n"
        : "+f"(c[0]), "+f"(c[1]), "+f"(c[2]), "+f"(c[3])
        : "r"(a[0]), "r"(a[1]), "r"(a[2]), "r"(a[3]), "r"(b[0]), "r"(b[1]));
}

// ===========================================================================
// tf32 mma.sync GEMM with bias (UNCHANGED — passing at 2347us config)
// ===========================================================================
constexpr int BM = 128, BN = 128, BK = 32;
constexpr int ASTR = BK + 4;
constexpr int BSTR = BN + 8;
constexpr int ABUF = BM * ASTR;
constexpr int BBUF = BK * BSTR;
constexpr unsigned SMEM_TOTAL_G = 2u * (ABUF + BBUF) * 4u;   // 71680 bytes

__global__ __launch_bounds__(256)
void tf32_mma_gemm_bias(const float* __restrict__ A, const float* __restrict__ Bm,
                        const float* __restrict__ bias, float* __restrict__ C,
                        int M, int N, int K) {
    extern __shared__ unsigned smemu[];

    const int tid  = threadIdx.x;
    const int warp = tid >> 5;
    const int lane = tid & 31;
    const int wm   = warp >> 2;
    const int wn   = warp & 3;
    const int g    = lane >> 2;
    const int t    = lane & 3;

    const float* Ag = A  + (size_t)blockIdx.y * BM * K;
    const float* Bg = Bm + (size_t)blockIdx.x * BN;

    int arow[4], ac4[4], brow[4], bc4[4];
    #pragma unroll
    for (int i = 0; i < 4; ++i) {
        int f4 = tid + i * 256;
        arow[i] = f4 >> 3;  ac4[i] = f4 & 7;
        brow[i] = f4 >> 5;  bc4[i] = f4 & 31;
    }

    float acc[4][4][4];
    #pragma unroll
    for (int mt = 0; mt < 4; ++mt)
        #pragma unroll
        for (int nt = 0; nt < 4; ++nt)
            #pragma unroll
            for (int j = 0; j < 4; ++j) acc[mt][nt][j] = 0.f;

    const int nchunks = K / BK;
    float4 ra[4], rb[4];

    #pragma unroll
    for (int i = 0; i < 4; ++i)
        ra[i] = *(const float4*)(Ag + (size_t)arow[i] * K + ac4[i] * 4);
    #pragma unroll
    for (int i = 0; i < 4; ++i)
        rb[i] = *(const float4*)(Bg + (size_t)brow[i] * N + bc4[i] * 4);

    {
        unsigned* sA = smemu;
        unsigned* sB = smemu + ABUF;
        #pragma unroll
        for (int i = 0; i < 4; ++i) {
            unsigned* d = sA + arow[i] * ASTR + ac4[i] * 4;
            d[0] = f2tf32(ra[i].x); d[1] = f2tf32(ra[i].y);
            d[2] = f2tf32(ra[i].z); d[3] = f2tf32(ra[i].w);
        }
        #pragma unroll
        for (int i = 0; i < 4; ++i) {
            unsigned* d = sB + brow[i] * BSTR + bc4[i] * 4;
            d[0] = f2tf32(rb[i].x); d[1] = f2tf32(rb[i].y);
            d[2] = f2tf32(rb[i].z); d[3] = f2tf32(rb[i].w);
        }
    }
    __syncthreads();

    for (int c = 0; c < nchunks; ++c) {
        if (c + 1 < nchunks) {
            const int kn = (c + 1) * BK;
            #pragma unroll
            for (int i = 0; i < 4; ++i)
                ra[i] = *(const float4*)(Ag + (size_t)arow[i] * K + kn + ac4[i] * 4);
            #pragma unroll
            for (int i = 0; i < 4; ++i)
                rb[i] = *(const float4*)(Bg + (size_t)(kn + brow[i]) * N + bc4[i] * 4);
        }

        {
            const unsigned* sA = smemu + (c & 1) * (ABUF + BBUF);
            const unsigned* sB = sA + ABUF;
            #pragma unroll
            for (int ks = 0; ks < 4; ++ks) {
                unsigned af[4][4], bf[4][2];
                #pragma unroll
                for (int mt = 0; mt < 4; ++mt) {
                    const int base = (wm * 64 + mt * 16 + g) * ASTR + ks * 8 + t;
                    af[mt][0] = sA[base];
                    af[mt][1] = sA[base + 8 * ASTR];
                    af[mt][2] = sA[base + 4];
                    af[mt][3] = sA[base + 8 * ASTR + 4];
                }
                #pragma unroll
                for (int nt = 0; nt < 4; ++nt) {
                    const int bbase = (ks * 8 + t) * BSTR + wn * 32 + nt * 8 + g;
                    bf[nt][0] = sB[bbase];
                    bf[nt][1] = sB[bbase + 4 * BSTR];
                }
                #pragma unroll
                for (int mt = 0; mt < 4; ++mt)
                    #pragma unroll
                    for (int nt = 0; nt < 4; ++nt)
                        mma_tf32(acc[mt][nt], af[mt], bf[nt]);
            }
        }

        if (c + 1 < nchunks) {
            unsigned* sA = smemu + ((c + 1) & 1) * (ABUF + BBUF);
            unsigned* sB = sA + ABUF;
            #pragma unroll
            for (int i = 0; i < 4; ++i) {
                unsigned* d = sA + arow[i] * ASTR + ac4[i] * 4;
                d[0] = f2tf32(ra[i].x); d[1] = f2tf32(ra[i].y);
                d[2] = f2tf32(ra[i].z); d[3] = f2tf32(ra[i].w);
            }
            #pragma unroll
            for (int i = 0; i < 4; ++i) {
                unsigned* d = sB + brow[i] * BSTR + bc4[i] * 4;
                d[0] = f2tf32(rb[i].x); d[1] = f2tf32(rb[i].y);
                d[2] = f2tf32(rb[i].z); d[3] = f2tf32(rb[i].w);
            }
            __syncthreads();
        }
    }

    const int rowb = blockIdx.y * BM;
    const int colb = blockIdx.x * BN;
    #pragma unroll
    for (int mt = 0; mt < 4; ++mt) {
        const int row0 = rowb + wm * 64 + mt * 16 + g;
        #pragma unroll
        for (int nt = 0; nt < 4; ++nt) {
            const int col = colb + wn * 32 + nt * 8 + 2 * t;
            float2 bb = *(const float2*)(bias + col);
            float2 v0, v1;
            v0.x = acc[mt][nt][0] + bb.x;  v0.y = acc[mt][nt][1] + bb.y;
            v1.x = acc[mt][nt][2] + bb.x;  v1.y = acc[mt][nt][3] + bb.y;
            *(float2*)(C + (size_t)row0 * N + col)       = v0;
            *(float2*)(C + (size_t)(row0 + 8) * N + col) = v1;
        }
    }
}

// ===========================================================================
// Causal flash attention with tf32 mma.sync (UNTESTED — resubmitting).
// 1 block = 64 q-rows x (h,b). 128 threads = 4 warps, warp owns 16 q-rows.
// ===========================================================================
constexpr int KS_W = 68, VT_W = 67, PS_W = 68;
constexpr unsigned SMEM_AT = (64u * KS_W + 64u * VT_W + 64u * PS_W) * 4u; // 51968

__global__ __launch_bounds__(128)
void flash_attn_mma(const float* __restrict__ qkv, float* __restrict__ ans) {
    extern __shared__ unsigned smat[];
    unsigned* Ks = smat;
    unsigned* Vt = smat + 64 * KS_W;
    unsigned* Ps = smat + 64 * KS_W + 64 * VT_W;

    const int qt = blockIdx.x, h = blockIdx.y, b = blockIdx.z;
    const int q0 = qt * 64;
    const int tid = threadIdx.x, warp = tid >> 5, lane = tid & 31;
    const int g = lane >> 2, t = lane & 3;
    const int wrow = warp * 16;

    // Stage Q (scale 0.125 folded, tf32) via Ps, preload fragments to regs
    for (int idx = tid; idx < 64 * 16; idx += 128) {
        int r = idx >> 4, e4 = idx & 15;
        float4 v = *(const float4*)(qkv + (size_t)(b * Ss + q0 + r) * QKV_N + h * DHh + e4 * 4);
        unsigned* d = Ps + r * PS_W + e4 * 4;
        d[0] = f2tf32(v.x * 0.125f); d[1] = f2tf32(v.y * 0.125f);
        d[2] = f2tf32(v.z * 0.125f); d[3] = f2tf32(v.w * 0.125f);
    }
    __syncthreads();
    unsigned qf[8][4];
    #pragma unroll
    for (int k8 = 0; k8 < 8; ++k8) {
        int base = (wrow + g) * PS_W + k8 * 8 + t;
        qf[k8][0] = Ps[base];           qf[k8][1] = Ps[base + 8 * PS_W];
        qf[k8][2] = Ps[base + 4];       qf[k8][3] = Ps[base + 8 * PS_W + 4];
    }

    float o[8][4];
    #pragma unroll
    for (int n = 0; n < 8; ++n)
        #pragma unroll
        for (int j = 0; j < 4; ++j) o[n][j] = 0.f;
    float m0 = -INFINITY, m1 = -INFINITY, l0 = 0.f, l1 = 0.f;

    for (int kt = 0; kt <= qt; ++kt) {
        const int k0 = kt * 64;
        __syncthreads();   // prior iter's Ks/Vt reads (and Q-stage) done
        for (int idx = tid; idx < 64 * 16; idx += 128) {
            int r = idx >> 4, e4 = idx & 15;
            size_t base = (size_t)(b * Ss + k0 + r) * QKV_N + h * DHh + e4 * 4;
            float4 kv = *(const float4*)(qkv + base + Hh * DHh);
            float4 vv = *(const float4*)(qkv + base + 2 * Hh * DHh);
            unsigned* d = Ks + r * KS_W + e4 * 4;
            d[0] = f2tf32(kv.x); d[1] = f2tf32(kv.y);
            d[2] = f2tf32(kv.z); d[3] = f2tf32(kv.w);
            Vt[(e4 * 4 + 0) * VT_W + r] = f2tf32(vv.x);
            Vt[(e4 * 4 + 1) * VT_W + r] = f2tf32(vv.y);
            Vt[(e4 * 4 + 2) * VT_W + r] = f2tf32(vv.z);
            Vt[(e4 * 4 + 3) * VT_W + r] = f2tf32(vv.w);
        }
        __syncthreads();

        // S = Q @ K^T  (warp: 16 rows x 64 keys)
        float sacc[8][4];
        #pragma unroll
        for (int n = 0; n < 8; ++n)
            #pragma unroll
            for (int j = 0; j < 4; ++j) sacc[n][j] = 0.f;
        #pragma unroll
        for (int k8 = 0; k8 < 8; ++k8) {
            #pragma unroll
            for (int n = 0; n < 8; ++n) {
                unsigned bf[2];
                int bb = (n * 8 + g) * KS_W + k8 * 8 + t;
                bf[0] = Ks[bb]; bf[1] = Ks[bb + 4];
                mma_tf32(sacc[n], qf[k8], bf);
            }
        }

        // Causal mask (diagonal tile only)
        if (kt == qt) {
            #pragma unroll
            for (int n = 0; n < 8; ++n) {
                int c0 = k0 + n * 8 + 2 * t;
                int r0 = q0 + wrow + g;
                if (c0     > r0)     sacc[n][0] = -1e30f;
                if (c0 + 1 > r0)     sacc[n][1] = -1e30f;
                if (c0     > r0 + 8) sacc[n][2] = -1e30f;
                if (c0 + 1 > r0 + 8) sacc[n][3] = -1e30f;
            }
        }

        // Online softmax: rows g (m0/l0) and g+8 (m1/l1); quad reduce
        float mx0 = -1e30f, mx1 = -1e30f;
        #pragma unroll
        for (int n = 0; n < 8; ++n) {
            mx0 = fmaxf(mx0, fmaxf(sacc[n][0], sacc[n][1]));
            mx1 = fmaxf(mx1, fmaxf(sacc[n][2], sacc[n][3]));
        }
        mx0 = fmaxf(mx0, __shfl_xor_sync(0xffffffffu, mx0, 1));
        mx0 = fmaxf(mx0, __shfl_xor_sync(0xffffffffu, mx0, 2));
        mx1 = fmaxf(mx1, __shfl_xor_sync(0xffffffffu, mx1, 1));
        mx1 = fmaxf(mx1, __shfl_xor_sync(0xffffffffu, mx1, 2));
        float mn0 = fmaxf(m0, mx0), mn1 = fmaxf(m1, mx1);
        float rs0 = 0.f, rs1 = 0.f;
        #pragma unroll
        for (int n = 0; n < 8; ++n) {
            sacc[n][0] = __expf(sacc[n][0] - mn0);
            sacc[n][1] = __expf(sacc[n][1] - mn0);
            sacc[n][2] = __expf(sacc[n][2] - mn1);
            sacc[n][3] = __expf(sacc[n][3] - mn1);
            rs0 += sacc[n][0] + sacc[n][1];
            rs1 += sacc[n][2] + sacc[n][3];
        }
        rs0 += __shfl_xor_sync(0xffffffffu, rs0, 1);
        rs0 += __shfl_xor_sync(0xffffffffu, rs0, 2);
        rs1 += __shfl_xor_sync(0xffffffffu, rs1, 1);
        rs1 += __shfl_xor_sync(0xffffffffu, rs1, 2);
        float a0 = __expf(m0 - mn0), a1 = __expf(m1 - mn1);
        l0 = l0 * a0 + rs0;  l1 = l1 * a1 + rs1;
        m0 = mn0;            m1 = mn1;
        #pragma unroll
        for (int n = 0; n < 8; ++n) {
            o[n][0] *= a0; o[n][1] *= a0; o[n][2] *= a1; o[n][3] *= a1;
        }

        // P -> smem (warp-private rows), then PV
        #pragma unroll
        for (int n = 0; n < 8; ++n) {
            int pr = (wrow + g) * PS_W + n * 8 + 2 * t;
            Ps[pr]              = f2tf32(sacc[n][0]);
            Ps[pr + 1]          = f2tf32(sacc[n][1]);
            Ps[pr + 8 * PS_W]     = f2tf32(sacc[n][2]);
            Ps[pr + 8 * PS_W + 1] = f2tf32(sacc[n][3]);
        }
        __syncwarp();

        #pragma unroll
        for (int k8 = 0; k8 < 8; ++k8) {
            unsigned af[4];
            int ab = (wrow + g) * PS_W + k8 * 8 + t;
            af[0] = Ps[ab];     af[1] = Ps[ab + 8 * PS_W];
            af[2] = Ps[ab + 4]; af[3] = Ps[ab + 8 * PS_W + 4];
            #pragma unroll
            for (int n = 0; n < 8; ++n) {
                unsigned bf[2];
                int bb = (n * 8 + g) * VT_W + k8 * 8 + t;
                bf[0] = Vt[bb]; bf[1] = Vt[bb + 4];
                mma_tf32(o[n], af, bf);
            }
        }
        __syncwarp();
    }

    // Normalize, store ans[b,s,h,e]
    float inv0 = 1.f / l0, inv1 = 1.f / l1;
    #pragma unroll
    for (int n = 0; n < 8; ++n) {
        int col = n * 8 + 2 * t;
        int r0 = q0 + wrow + g;
        float2 v0 = make_float2(o[n][0] * inv0, o[n][1] * inv0);
        float2 v1 = make_float2(o[n][2] * inv1, o[n][3] * inv1);
        *(float2*)(ans + ((size_t)(b * Ss + r0) * Hh + h) * DHh + col)     = v0;
        *(float2*)(ans + ((size_t)(b * Ss + r0 + 8) * Hh + h) * DHh + col) = v1;
    }
}

// ---------------------------------------------------------------------------
// Launch
// ---------------------------------------------------------------------------
extern "C" void kernel_launch(void* const* d_in, const int* in_sizes, int n_in,
                              void* d_out, int out_size) {
    const float* x     = (const float*)d_in[0];
    const float* w_qkv = (const float*)d_in[1];
    const float* b_qkv = (const float*)d_in[2];
    const float* w_out = (const float*)d_in[3];
    const float* b_out = (const float*)d_in[4];
    float* out = (float*)d_out;

    void* qkv_ptr = nullptr;
    void* ans_ptr = nullptr;
    cudaGetSymbolAddress(&qkv_ptr, g_qkv);
    cudaGetSymbolAddress(&ans_ptr, g_ans);
    float* qkv = (float*)qkv_ptr;
    float* ans = (float*)ans_ptr;

    cudaFuncSetAttribute(tf32_mma_gemm_bias,
                         cudaFuncAttributeMaxDynamicSharedMemorySize,
                         (int)SMEM_TOTAL_G);
    cudaFuncSetAttribute(flash_attn_mma,
                         cudaFuncAttributeMaxDynamicSharedMemorySize,
                         (int)SMEM_AT);

    // 1) QKV projection (tf32 mma.sync)
    {
        dim3 grid(QKV_N / 128, Mrows / 128);
        tf32_mma_gemm_bias<<<grid, 256, SMEM_TOTAL_G>>>(
            x, w_qkv, b_qkv, qkv, Mrows, QKV_N, Dd);
    }

    // 2) Causal flash attention (tf32 mma.sync)
    {
        dim3 grid(Ss / 64, Hh, Bb);
        flash_attn_mma<<<grid, 128, SMEM_AT>>>(qkv, ans);
    }

    // 3) Output projection (tf32 mma.sync)
    {
        dim3 grid(Dd / 128, Mrows / 128);
        tf32_mma_gemm_bias<<<grid, 256, SMEM_TOTAL_G>>>(
            ans, w_out, b_out, out, Mrows, Dd, Dd);
    }
}